// round 1
// baseline (speedup 1.0000x reference)
#include <cuda_runtime.h>
#include <cmath>

// Problem constants (fixed by setup_inputs)
#define NG    8192        // total genes
#define BGRP  16          // groups
#define GS    512         // group size
#define DIM   768         // hidden dim

// Scratch (no allocations allowed -> __device__ globals)
__device__ float g_Q[NG * DIM];
__device__ float g_K[NG * DIM];
__device__ float g_V[NG * DIM];
__device__ float g_S[BGRP * GS * GS];   // scores / probs (in-place softmax)
__device__ float g_DYN[NG * DIM];

// ---------------------------------------------------------------------------
// GEMM NT: C[M,N] = A[M,K] @ B[N,K]^T  (both row-major, K contiguous)
// MODE 0: C = acc + bias[n]                      (QKV projections)
// MODE 1: C = acc * scale                        (scores, batched over z)
// MODE 2: C = X + beta[0] * (acc + bias[n])      (output projection + residual)
// Tiles: BM=BN=128, BK=16, 256 threads, 8x8 per thread. All dims divide evenly.
// ---------------------------------------------------------------------------
template <int MODE>
__global__ __launch_bounds__(256)
void gemm_nt(const float* __restrict__ A, const float* __restrict__ B,
             const float* __restrict__ bias, float* __restrict__ C,
             int K, int lda, int ldb, int ldc,
             long strideA, long strideB, long strideC,
             float scale,
             const float* __restrict__ X, const float* __restrict__ beta)
{
    const int BM = 128, BN = 128, BK = 16, TM = 8, TN = 8;
    __shared__ float As[BK][BM];
    __shared__ float Bs[BK][BN];

    const int bz = blockIdx.z;
    A += bz * strideA;  B += bz * strideB;  C += bz * strideC;

    const int row0 = blockIdx.y * BM;
    const int col0 = blockIdx.x * BN;
    const int tid = threadIdx.x;
    const int tx = tid & 15;        // 16 thread-cols
    const int ty = tid >> 4;        // 16 thread-rows

    float acc[TM][TN];
#pragma unroll
    for (int i = 0; i < TM; i++)
#pragma unroll
        for (int j = 0; j < TN; j++) acc[i][j] = 0.f;

    for (int k0 = 0; k0 < K; k0 += BK) {
        // Load A tile: 128x16 floats = 512 float4 (2 per thread), store transposed
#pragma unroll
        for (int i = 0; i < 2; i++) {
            int idx = tid + i * 256;
            int r = idx >> 2, c4 = (idx & 3) << 2;
            float4 v = *(const float4*)(A + (long)(row0 + r) * lda + k0 + c4);
            As[c4 + 0][r] = v.x; As[c4 + 1][r] = v.y;
            As[c4 + 2][r] = v.z; As[c4 + 3][r] = v.w;
        }
        // Load B tile: 128x16 floats, transposed
#pragma unroll
        for (int i = 0; i < 2; i++) {
            int idx = tid + i * 256;
            int r = idx >> 2, c4 = (idx & 3) << 2;
            float4 v = *(const float4*)(B + (long)(col0 + r) * ldb + k0 + c4);
            Bs[c4 + 0][r] = v.x; Bs[c4 + 1][r] = v.y;
            Bs[c4 + 2][r] = v.z; Bs[c4 + 3][r] = v.w;
        }
        __syncthreads();

#pragma unroll
        for (int kk = 0; kk < BK; kk++) {
            float a[TM], b[TN];
            float4 a0 = *(const float4*)&As[kk][ty * TM];
            float4 a1 = *(const float4*)&As[kk][ty * TM + 4];
            a[0]=a0.x; a[1]=a0.y; a[2]=a0.z; a[3]=a0.w;
            a[4]=a1.x; a[5]=a1.y; a[6]=a1.z; a[7]=a1.w;
            float4 b0 = *(const float4*)&Bs[kk][tx * TN];
            float4 b1 = *(const float4*)&Bs[kk][tx * TN + 4];
            b[0]=b0.x; b[1]=b0.y; b[2]=b0.z; b[3]=b0.w;
            b[4]=b1.x; b[5]=b1.y; b[6]=b1.z; b[7]=b1.w;
#pragma unroll
            for (int i = 0; i < TM; i++)
#pragma unroll
                for (int j = 0; j < TN; j++)
                    acc[i][j] = fmaf(a[i], b[j], acc[i][j]);
        }
        __syncthreads();
    }

    // Epilogue
    float betav = 0.f;
    if (MODE == 2) betav = beta[0];

#pragma unroll
    for (int i = 0; i < TM; i++) {
        int r = row0 + ty * TM + i;
#pragma unroll
        for (int jj = 0; jj < TN; jj += 4) {
            int c = col0 + tx * TN + jj;
            float4 v;
            v.x = acc[i][jj + 0]; v.y = acc[i][jj + 1];
            v.z = acc[i][jj + 2]; v.w = acc[i][jj + 3];
            if (MODE == 0) {
                v.x += bias[c + 0]; v.y += bias[c + 1];
                v.z += bias[c + 2]; v.w += bias[c + 3];
            } else if (MODE == 1) {
                v.x *= scale; v.y *= scale; v.z *= scale; v.w *= scale;
            } else {
                const float4 xb = *(const float4*)(X + (long)r * ldc + c);
                v.x = xb.x + betav * (v.x + bias[c + 0]);
                v.y = xb.y + betav * (v.y + bias[c + 1]);
                v.z = xb.z + betav * (v.z + bias[c + 2]);
                v.w = xb.w + betav * (v.w + bias[c + 3]);
            }
            *(float4*)(C + (long)r * ldc + c) = v;
        }
    }
}

// ---------------------------------------------------------------------------
// GEMM NN: C[M,N] = A[M,K] @ B[K,N]   (P @ V, batched over z)
// ---------------------------------------------------------------------------
__global__ __launch_bounds__(256)
void gemm_nn(const float* __restrict__ A, const float* __restrict__ B,
             float* __restrict__ C,
             int K, int lda, int ldb, int ldc,
             long strideA, long strideB, long strideC)
{
    const int BM = 128, BN = 128, BK = 16, TM = 8, TN = 8;
    __shared__ float As[BK][BM];
    __shared__ float Bs[BK][BN];

    const int bz = blockIdx.z;
    A += bz * strideA;  B += bz * strideB;  C += bz * strideC;

    const int row0 = blockIdx.y * BM;
    const int col0 = blockIdx.x * BN;
    const int tid = threadIdx.x;
    const int tx = tid & 15;
    const int ty = tid >> 4;

    float acc[TM][TN];
#pragma unroll
    for (int i = 0; i < TM; i++)
#pragma unroll
        for (int j = 0; j < TN; j++) acc[i][j] = 0.f;

    for (int k0 = 0; k0 < K; k0 += BK) {
        // A tile (transposed into smem)
#pragma unroll
        for (int i = 0; i < 2; i++) {
            int idx = tid + i * 256;
            int r = idx >> 2, c4 = (idx & 3) << 2;
            float4 v = *(const float4*)(A + (long)(row0 + r) * lda + k0 + c4);
            As[c4 + 0][r] = v.x; As[c4 + 1][r] = v.y;
            As[c4 + 2][r] = v.z; As[c4 + 3][r] = v.w;
        }
        // B tile: [BK rows x BN cols], direct layout, coalesced along N
#pragma unroll
        for (int i = 0; i < 2; i++) {
            int idx = tid + i * 256;
            int r = idx >> 5, c4 = (idx & 31) << 2;
            float4 v = *(const float4*)(B + (long)(k0 + r) * ldb + col0 + c4);
            *(float4*)&Bs[r][c4] = v;
        }
        __syncthreads();

#pragma unroll
        for (int kk = 0; kk < BK; kk++) {
            float a[TM], b[TN];
            float4 a0 = *(const float4*)&As[kk][ty * TM];
            float4 a1 = *(const float4*)&As[kk][ty * TM + 4];
            a[0]=a0.x; a[1]=a0.y; a[2]=a0.z; a[3]=a0.w;
            a[4]=a1.x; a[5]=a1.y; a[6]=a1.z; a[7]=a1.w;
            float4 b0 = *(const float4*)&Bs[kk][tx * TN];
            float4 b1 = *(const float4*)&Bs[kk][tx * TN + 4];
            b[0]=b0.x; b[1]=b0.y; b[2]=b0.z; b[3]=b0.w;
            b[4]=b1.x; b[5]=b1.y; b[6]=b1.z; b[7]=b1.w;
#pragma unroll
            for (int i = 0; i < TM; i++)
#pragma unroll
                for (int j = 0; j < TN; j++)
                    acc[i][j] = fmaf(a[i], b[j], acc[i][j]);
        }
        __syncthreads();
    }

#pragma unroll
    for (int i = 0; i < TM; i++) {
        int r = row0 + ty * TM + i;
#pragma unroll
        for (int jj = 0; jj < TN; jj += 4) {
            int c = col0 + tx * TN + jj;
            float4 v;
            v.x = acc[i][jj + 0]; v.y = acc[i][jj + 1];
            v.z = acc[i][jj + 2]; v.w = acc[i][jj + 3];
            *(float4*)(C + (long)r * ldc + c) = v;
        }
    }
}

// ---------------------------------------------------------------------------
// Row softmax over group (512 keys), diagonal self-masked. In-place on g_S.
// One CTA (128 threads) per row; 4 elements per thread.
// ---------------------------------------------------------------------------
__global__ __launch_bounds__(128)
void softmax_rows(float* __restrict__ S)
{
    const int row = blockIdx.x;            // 0..8191
    const int g = row >> 9;
    const int r = row & 511;
    float* p = S + ((long)g << 18) + ((long)r << 9);
    const int tid = threadIdx.x;
    const int w = tid >> 5, l = tid & 31;

    float v[4];
    float mx = -INFINITY;
#pragma unroll
    for (int i = 0; i < 4; i++) {
        int j = tid + (i << 7);
        float t = p[j];
        if (j == r) t = -INFINITY;          // self mask
        v[i] = t;
        mx = fmaxf(mx, t);
    }
#pragma unroll
    for (int o = 16; o; o >>= 1) mx = fmaxf(mx, __shfl_xor_sync(0xffffffffu, mx, o));
    __shared__ float sm[4], ss[4];
    if (l == 0) sm[w] = mx;
    __syncthreads();
    mx = fmaxf(fmaxf(sm[0], sm[1]), fmaxf(sm[2], sm[3]));

    float sum = 0.f;
#pragma unroll
    for (int i = 0; i < 4; i++) { v[i] = __expf(v[i] - mx); sum += v[i]; }
#pragma unroll
    for (int o = 16; o; o >>= 1) sum += __shfl_xor_sync(0xffffffffu, sum, o);
    if (l == 0) ss[w] = sum;
    __syncthreads();
    sum = ss[0] + ss[1] + ss[2] + ss[3];
    const float inv = 1.f / sum;
#pragma unroll
    for (int i = 0; i < 4; i++) p[tid + (i << 7)] = v[i] * inv;
}

// ---------------------------------------------------------------------------
// Launcher
// Inputs (metadata order): gene_embeddings, batch(int64, unused — groups are
// contiguous 512), Wq, bq, Wk, bk, Wv, bv, Wo, bo, beta.
// ---------------------------------------------------------------------------
extern "C" void kernel_launch(void* const* d_in, const int* in_sizes, int n_in,
                              void* d_out, int out_size)
{
    (void)in_sizes; (void)n_in; (void)out_size;
    const float* x    = (const float*)d_in[0];
    const float* Wq   = (const float*)d_in[2];
    const float* bq   = (const float*)d_in[3];
    const float* Wk   = (const float*)d_in[4];
    const float* bk   = (const float*)d_in[5];
    const float* Wv   = (const float*)d_in[6];
    const float* bv   = (const float*)d_in[7];
    const float* Wo   = (const float*)d_in[8];
    const float* bo   = (const float*)d_in[9];
    const float* beta = (const float*)d_in[10];
    float* out = (float*)d_out;

    float *Q, *K, *V, *S, *DYN;
    cudaGetSymbolAddress((void**)&Q,   g_Q);
    cudaGetSymbolAddress((void**)&K,   g_K);
    cudaGetSymbolAddress((void**)&V,   g_V);
    cudaGetSymbolAddress((void**)&S,   g_S);
    cudaGetSymbolAddress((void**)&DYN, g_DYN);

    const dim3 blk(256);
    const float scale = 1.0f / sqrtf((float)DIM);

    // Q/K/V projections: [8192,768] @ [768,768]^T + bias
    gemm_nt<0><<<dim3(6, 64, 1), blk>>>(x, Wq, bq, Q, DIM, DIM, DIM, DIM,
                                        0, 0, 0, 1.f, nullptr, nullptr);
    gemm_nt<0><<<dim3(6, 64, 1), blk>>>(x, Wk, bk, K, DIM, DIM, DIM, DIM,
                                        0, 0, 0, 1.f, nullptr, nullptr);
    gemm_nt<0><<<dim3(6, 64, 1), blk>>>(x, Wv, bv, V, DIM, DIM, DIM, DIM,
                                        0, 0, 0, 1.f, nullptr, nullptr);

    // Per-group scores: S_g = Q_g @ K_g^T * scale   (batched z=16)
    gemm_nt<1><<<dim3(4, 4, BGRP), blk>>>(Q, K, nullptr, S, DIM, DIM, DIM, GS,
                                          (long)GS * DIM, (long)GS * DIM,
                                          (long)GS * GS, scale, nullptr, nullptr);

    // Masked softmax per row (in place)
    softmax_rows<<<NG, 128>>>(S);

    // Per-group P @ V  (batched z=16)
    gemm_nn<<<dim3(6, 4, BGRP), blk>>>(S, V, DYN, GS, GS, DIM, DIM,
                                       (long)GS * GS, (long)GS * DIM,
                                       (long)GS * DIM);

    // Output projection + residual: out = x + beta*(DYN @ Wo^T + bo)
    gemm_nt<2><<<dim3(6, 64, 1), blk>>>(DYN, Wo, bo, out, DIM, DIM, DIM, DIM,
                                        0, 0, 0, 1.f, x, beta);
}